// round 8
// baseline (speedup 1.0000x reference)
#include <cuda_runtime.h>
#include <cuda_pipeline.h>
#include <math.h>

#define NSC   48
#define RMAX  11
#define NCTA  (3*NSC)
#define T     384

#define GW0_F4 (76*64)     // 4864 f4 per scale
#define GW0_C  2432        // gw0 chunk (38 k-rows)
#define GW1_F4 (128*64)    // 8192 f4 per scale
#define GW1_C  4096        // gw1 chunk (64 k-rows)
#define PAN_F4 4096        // each ping-pong buffer 64KB
#define DYN_SMEM (2*PAN_F4*16)   // 131072 bytes

__device__ float4 g_gw0p[3*GW0_F4];
__device__ float4 g_gw1p[3*GW1_F4];
__device__ __align__(16) float  g_Wa[6*64*64];
__device__ float  g_ba[6*64];
__device__ float  g_outs[3ull*512*512*64];

__device__ __forceinline__ float sigmf(float v){
    return __fdividef(1.0f, 1.0f + __expf(-v));
}
__device__ __forceinline__ float tanhfast(float v){
    return 1.0f - __fdividef(2.0f, __expf(2.0f*v) + 1.0f);
}

template<int N>
__device__ __forceinline__ void cpy_async(float4* d, const float4* __restrict__ s, int tid){
    #pragma unroll
    for (int i = 0; i < (N + T - 1)/T; i++){
        int j = tid + i*T;
        if (j < N) __pipeline_memcpy_async(d + j, s + j, 16);
    }
    __pipeline_commit();
}
#define PWAIT() do{ __pipeline_wait_prior(0); __syncthreads(); }while(0)

__global__ void pack_gw_kernel(const float* __restrict__ gw0, const float* __restrict__ gw1){
    int i = blockIdx.x*blockDim.x + threadIdx.x;
    float* p0 = (float*)g_gw0p;
    float* p1 = (float*)g_gw1p;
    if (i < 3*76*256){
        int s = i/(76*256), rem = i%(76*256), k = rem/256, j = rem%256;
        p0[(s*76 + k)*256 + ((j&63)<<2) + (j>>6)] = gw0[i];
    }
    if (i < 3*128*256){
        int s = i/(128*256), rem = i%(128*256), k = rem/256, j = rem%256;
        p1[(s*128 + k)*256 + ((j&63)<<2) + (j>>6)] = gw1[i];
    }
}

__global__ void compute_wa_kernel(const float* __restrict__ mi_w, const float* __restrict__ mi_b,
                                  const float* __restrict__ mo_w, const float* __restrict__ mo_b){
    int sl = blockIdx.x;
    const float* miw = mi_w + (size_t)sl*64*192;
    const float* mow = mo_w + (size_t)sl*64*64;
    for (int idx = threadIdx.x; idx < 64*64; idx += blockDim.x){
        int k = idx>>6, n = idx&63;
        float acc = 0.f;
        #pragma unroll 8
        for (int j=0;j<64;j++) acc += miw[k*192 + 128 + j] * mow[j*64 + n];
        g_Wa[sl*4096 + k*64 + n] = acc;
    }
    if (threadIdx.x < 64){
        int n = threadIdx.x;
        float acc = mo_b[sl*64 + n];
        #pragma unroll 8
        for (int j=0;j<64;j++) acc += mi_b[sl*192 + 128 + j] * mow[j*64 + n];
        g_ba[sl*64 + n] = acc;
    }
}

__global__ void __launch_bounds__(T, 1) xlstm_kernel(
    const float* __restrict__ x,
    const float* __restrict__ gb0, const float* __restrict__ gb1,
    const float* __restrict__ w1,  const float* __restrict__ b1,
    const float* __restrict__ w2,  const float* __restrict__ b2,
    const float* __restrict__ lag, const float* __restrict__ lab,
    const float* __restrict__ logw,const float* __restrict__ lob,
    const float* __restrict__ rw0, const float* __restrict__ rb0,
    const float* __restrict__ rw1, const float* __restrict__ rb1)
{
    const int cta = blockIdx.x;
    const int s   = cta / NSC;
    const int ci  = cta % NSC;
    const int base  = (ci < 32) ? ci*11 : 352 + (ci-32)*10;
    const int nrows = (ci < 32) ? 11 : 10;
    const int tid  = threadIdx.x;
    const int m    = tid & 63;
    const int rg   = tid >> 6;
    const int lane = tid & 31;
    const int wrp  = tid >> 5;
    const int cg   = tid & 31;
    const int m2   = cg*2;
    const int cgf  = tid & 63;
    const int n2b  = cgf*2;
    const int rgf  = tid >> 6;

    extern __shared__ float4 dynsm[];
    float4* bufA = dynsm;
    float4* bufB = dynsm + PAN_F4;

    __shared__ __align__(16) float sh_h0[RMAX][64], sh_h1[RMAX][64];
    __shared__ __align__(16) float sh_x[RMAX][12];
    __shared__ __align__(16) float sh_hy[RMAX][64];
    __shared__ __align__(16) float sh_a[RMAX][64];
    __shared__ __align__(16) float sh_t1[RMAX][128];
    __shared__ __align__(16) float sh_inp[RMAX][64];
    __shared__ float sh_stat[RMAX][2];
    __shared__ __align__(16) float sb_ba[2][64];
    __shared__ __align__(16) float sb_b1[2][128];
    __shared__ __align__(16) float sb_b2[2][64];
    __shared__ __align__(16) float sb_rb1[64];
    __shared__ __align__(16) float s_rw0[12*64];
    __shared__ __align__(16) float s_rw1[64*64];

    // ---- resident loads ----
    {
        const float* rw1s = rw1 + (size_t)s*4096;
        for (int i=tid;i<4096;i+=T) s_rw1[i] = rw1s[i];
        const float* rw0s = rw0 + (size_t)s*768;
        for (int i=tid;i<768;i+=T) s_rw0[i] = rw0s[i];
        for (int i = tid; i < RMAX*64; i += T){ ((float*)sh_h0)[i] = 0.f; ((float*)sh_h1)[i] = 0.f; }
        if (tid < 128){
            sb_b1[0][tid] = b1[(s*2+0)*128 + tid];
            sb_b1[1][tid] = b1[(s*2+1)*128 + tid];
        }
        if (tid < 64){
            sb_ba[0][tid] = g_ba[(s*2+0)*64 + tid];
            sb_ba[1][tid] = g_ba[(s*2+1)*64 + tid];
            sb_b2[0][tid] = b2[(s*2+0)*64 + tid];
            sb_b2[1][tid] = b2[(s*2+1)*64 + tid];
            sb_rb1[tid]   = rb1[s*64 + tid];
        }
    }
    const float r_gb0f = gb0[s*256 + m],     r_gb0i = gb0[s*256 + 64 + m];
    const float r_gb0g = gb0[s*256 + 128+m], r_gb0o = gb0[s*256 + 192 + m];
    const float r_gb1f = gb1[s*256 + m],     r_gb1i = gb1[s*256 + 64 + m];
    const float r_gb1g = gb1[s*256 + 128+m], r_gb1o = gb1[s*256 + 192 + m];
    const float r_lag0 = lag[(s*2+0)*64+m],  r_lag1 = lag[(s*2+1)*64+m];
    const float r_lab0 = lab[(s*2+0)*64+m],  r_lab1 = lab[(s*2+1)*64+m];
    const float r_log0 = logw[(s*2+0)*64+m], r_log1 = logw[(s*2+1)*64+m];
    const float r_lob0 = lob[(s*2+0)*64+m],  r_lob1 = lob[(s*2+1)*64+m];
    const float r_rb0  = rb0[s*64+m];
    __syncthreads();

    int myr[2]; int nmy = 0;
    #pragma unroll
    for (int q=0;q<2;q++){ int r = rg + 6*q; myr[q] = (r < nrows) ? r : (nrows-1); if (r < nrows) nmy = q+1; }
    const int rA = rgf;
    const int rBr = rgf + 6;
    const bool hasB = (rBr < nrows);
    const int rB = hasB ? rBr : 0;

    float c0r[2] = {0.f,0.f}, c1r[2] = {0.f,0.f};

    const float4* gw0g  = g_gw0p + (size_t)s*GW0_F4;
    const float4* gw1g  = g_gw1p + (size_t)s*GW1_F4;
    const float4* Wa0_4 = (const float4*)g_Wa + (size_t)(s*2+0)*1024;
    const float4* Wa1_4 = (const float4*)g_Wa + (size_t)(s*2+1)*1024;
    const float4* w10_4 = (const float4*)(w1 + (size_t)(s*2+0)*8192);
    const float4* w11_4 = (const float4*)(w1 + (size_t)(s*2+1)*8192);
    const float4* w20_4 = (const float4*)(w2 + (size_t)(s*2+0)*8192);
    const float4* w21_4 = (const float4*)(w2 + (size_t)(s*2+1)*8192);

    const int Li  = (s==0) ? 170 : (s==1 ? 512 : 256);
    const int st0 = (s==0) ? 342 : (s==1 ? 0   : 256);
    const float scf = (float)Li / 512.0f;

    float* outbase = g_outs + ((size_t)s*512 + base)*512*64;

    auto ln_pass = [&](){
        if (wrp < nrows){
            int r = wrp;
            float v0 = sh_hy[r][lane], v1 = sh_hy[r][lane+32];
            float sm = v0 + v1, sq = v0*v0 + v1*v1;
            #pragma unroll
            for (int o=16;o;o>>=1){
                sm += __shfl_xor_sync(0xffffffffu, sm, o);
                sq += __shfl_xor_sync(0xffffffffu, sq, o);
            }
            if (lane == 0){
                float mean = sm * 0.015625f;
                float var  = sq * 0.015625f - mean*mean;
                sh_stat[r][0] = mean;
                sh_stat[r][1] = rsqrtf(var + 1e-5f);
            }
        }
    };

    auto attn_stage = [&](int l, const float2* w){
        if (wrp < nrows){
            int r = wrp;
            float a0 = sb_ba[l][m2], a1 = sb_ba[l][m2+1];
            #pragma unroll 8
            for (int k=0;k<64;k++){
                float z = sh_hy[r][k];
                float2 wv = w[k*32 + cg];
                a0 += z*wv.x; a1 += z*wv.y;
            }
            *(float2*)&sh_a[r][m2] = make_float2(a0, a1);
        }
    };
    auto ff1_stage = [&](int l, const float2* w){
        float t00 = sb_b1[l][n2b], t01 = sb_b1[l][n2b+1];
        float t10 = t00, t11 = t01;
        #pragma unroll 8
        for (int k=0;k<64;k++){
            float z0 = sh_a[rA][k];
            float z1 = sh_a[rB][k];
            float2 wv = w[k*64 + cgf];
            t00 += z0*wv.x; t01 += z0*wv.y;
            t10 += z1*wv.x; t11 += z1*wv.y;
        }
        const float c = 0.7071067811865475f;
        float g00 = 0.5f*t00*(1.0f + erff(t00*c));
        float g01 = 0.5f*t01*(1.0f + erff(t01*c));
        *(float2*)&sh_t1[rA][n2b] = make_float2(g00, g01);
        if (hasB){
            float g10 = 0.5f*t10*(1.0f + erff(t10*c));
            float g11 = 0.5f*t11*(1.0f + erff(t11*c));
            *(float2*)&sh_t1[rB][n2b] = make_float2(g10, g11);
        }
    };
    auto ff2_stage = [&](int l, const float2* w){
        if (wrp < nrows){
            int r = wrp;
            float a0 = sb_b2[l][m2], a1 = sb_b2[l][m2+1];
            #pragma unroll 8
            for (int k=0;k<128;k++){
                float z = sh_t1[r][k];
                float2 wv = w[k*32 + cg];
                a0 += z*wv.x; a1 += z*wv.y;
            }
            *(float2*)&sh_hy[r][m2] = make_float2(a0, a1);
        }
    };
    auto ln_chain = [&](float (*hstate)[64], float* hn_out,
                        float lag_r, float lab_r, float log_r, float lob_r){
        ln_pass();
        __syncthreads();
        #pragma unroll
        for (int q=0;q<2;q++){
            int r = myr[q];
            float v  = sh_hy[r][m];
            float ln = (v - sh_stat[r][0]) * sh_stat[r][1] * lag_r + lab_r;
            float yv = ln + hstate[r][m];
            if (q < nmy) sh_hy[r][m] = yv;
        }
        __syncthreads();
        ln_pass();
        __syncthreads();
        #pragma unroll
        for (int q=0;q<2;q++){
            int r = myr[q];
            float yv = sh_hy[r][m];
            float hn = (yv - sh_stat[r][0]) * sh_stat[r][1] * log_r + lob_r;
            hn_out[q] = hn;
            if (q < nmy) hstate[r][m] = hn;
        }
    };

    // preload first panel: P0 = gw0 chunk A -> bufA
    cpy_async<GW0_C>(bufA, gw0g, tid);

    for (int t=0; t<512; t++){
        // x upsample (before P0 boundary; sync there publishes sh_x)
        {
            float srcf = fmaxf((t + 0.5f) * scf - 0.5f, 0.0f);
            int i0 = (int)srcf;
            if (i0 > Li-1) i0 = Li-1;
            int i1 = min(i0+1, Li-1);
            float wu = srcf - (float)i0;
            if (tid < nrows*12){
                int r = tid/12, k = tid%12;
                const float* xb = x + ((size_t)(base+r)*512 + st0)*12;
                float v0 = xb[i0*12 + k], v1 = xb[i1*12 + k];
                sh_x[r][k] = v0*(1.0f - wu) + v1*wu;
            }
        }
        PWAIT();                                        // P0 (gw0A) ready
        cpy_async<GW0_C>(bufB, gw0g + GW0_C, tid);      // issue P1

        // gates layer 0, part A (bufA): k 0..37
        float af[2], ai[2], ag[2], ao[2];
        #pragma unroll
        for (int q=0;q<2;q++){ af[q]=r_gb0f; ai[q]=r_gb0i; ag[q]=r_gb0g; ao[q]=r_gb0o; }
        #pragma unroll
        for (int k=0;k<12;k++){
            float4 wv = bufA[k*64 + m];
            #pragma unroll
            for (int q=0;q<2;q++){
                float z = sh_x[myr[q]][k];
                af[q] += z*wv.x; ai[q] += z*wv.y; ag[q] += z*wv.z; ao[q] += z*wv.w;
            }
        }
        #pragma unroll 8
        for (int k=12;k<38;k++){
            float4 wv = bufA[k*64 + m];
            #pragma unroll
            for (int q=0;q<2;q++){
                float z = sh_h0[myr[q]][k-12];
                af[q] += z*wv.x; ai[q] += z*wv.y; ag[q] += z*wv.z; ao[q] += z*wv.w;
            }
        }
        PWAIT();                                        // P1 (gw0B) ready
        cpy_async<1024>(bufA, Wa0_4, tid);              // issue P2

        #pragma unroll 8
        for (int k=38;k<76;k++){
            float4 wv = bufB[(k-38)*64 + m];
            #pragma unroll
            for (int q=0;q<2;q++){
                float z = sh_h0[myr[q]][k-12];
                af[q] += z*wv.x; ai[q] += z*wv.y; ag[q] += z*wv.z; ao[q] += z*wv.w;
            }
        }
        #pragma unroll
        for (int q=0;q<2;q++){
            float cn = sigmf(af[q])*c0r[q] + sigmf(ai[q])*tanhfast(ag[q]);
            float ht = sigmf(ao[q])*tanhfast(cn);
            if (q < nmy){ c0r[q] = cn; sh_hy[myr[q]][m] = ht; }
        }
        PWAIT();                                        // P2 (Wa0) ready; sh_hy visible
        cpy_async<2048>(bufB, w10_4, tid);              // issue P3
        attn_stage(0, (const float2*)bufA);
        PWAIT();                                        // P3 (w10) ready; sh_a visible
        cpy_async<2048>(bufA, w20_4, tid);              // issue P4
        ff1_stage(0, (const float2*)bufB);
        PWAIT();                                        // P4 (w20) ready; sh_t1 visible
        cpy_async<GW1_C>(bufB, gw1g, tid);              // issue P5 (gw1A)
        ff2_stage(0, (const float2*)bufA);
        __syncthreads();
        float h0n[2];
        ln_chain(sh_h0, h0n, r_lag0, r_lab0, r_log0, r_lob0);
        #pragma unroll
        for (int q=0;q<2;q++){
            int r = myr[q];
            float acc = h0n[q] + r_rb0;
            #pragma unroll
            for (int k=0;k<12;k++) acc += sh_x[r][k] * s_rw0[k*64 + m];
            if (q < nmy) sh_inp[r][m] = acc;
        }
        PWAIT();                                        // P5 (gw1A) ready; sh_inp visible
        cpy_async<GW1_C>(bufA, gw1g + GW1_C, tid);      // issue P6 (gw1B)

        // gates layer 1, part A (bufB): k 0..63 uses sh_inp
        float bf[2], bi[2], bg[2], bo[2];
        #pragma unroll
        for (int q=0;q<2;q++){ bf[q]=r_gb1f; bi[q]=r_gb1i; bg[q]=r_gb1g; bo[q]=r_gb1o; }
        #pragma unroll 8
        for (int k=0;k<64;k++){
            float4 wv = bufB[k*64 + m];
            #pragma unroll
            for (int q=0;q<2;q++){
                float z = sh_inp[myr[q]][k];
                bf[q] += z*wv.x; bi[q] += z*wv.y; bg[q] += z*wv.z; bo[q] += z*wv.w;
            }
        }
        PWAIT();                                        // P6 (gw1B) ready
        cpy_async<1024>(bufB, Wa1_4, tid);              // issue P7

        #pragma unroll 8
        for (int k=0;k<64;k++){
            float4 wv = bufA[k*64 + m];
            #pragma unroll
            for (int q=0;q<2;q++){
                float z = sh_h1[myr[q]][k];
                bf[q] += z*wv.x; bi[q] += z*wv.y; bg[q] += z*wv.z; bo[q] += z*wv.w;
            }
        }
        #pragma unroll
        for (int q=0;q<2;q++){
            float cn = sigmf(bf[q])*c1r[q] + sigmf(bi[q])*tanhfast(bg[q]);
            float ht = sigmf(bo[q])*tanhfast(cn);
            if (q < nmy){ c1r[q] = cn; sh_hy[myr[q]][m] = ht; }
        }
        PWAIT();                                        // P7 (Wa1) ready; sh_hy visible
        cpy_async<2048>(bufA, w11_4, tid);              // issue P8
        attn_stage(1, (const float2*)bufB);
        PWAIT();                                        // P8 (w11) ready; sh_a visible
        cpy_async<2048>(bufB, w21_4, tid);              // issue P9
        ff1_stage(1, (const float2*)bufA);
        PWAIT();                                        // P9 (w21) ready; sh_t1 visible
        cpy_async<GW0_C>(bufA, gw0g, tid);              // issue next-step P0 (gw0A)
        ff2_stage(1, (const float2*)bufB);
        __syncthreads();
        float h1n[2];
        ln_chain(sh_h1, h1n, r_lag1, r_lab1, r_log1, r_lob1);
        __syncthreads();                                // h1 visible for new-mapping out

        if (wrp < nrows){
            int r = wrp;
            float o0 = sh_h1[r][m2]   + sb_rb1[m2];
            float o1 = sh_h1[r][m2+1] + sb_rb1[m2+1];
            const float2* rw12 = (const float2*)s_rw1;
            #pragma unroll 8
            for (int k=0;k<64;k++){
                float z = sh_inp[r][k];
                float2 wv = rw12[k*32 + cg];
                o0 += z*wv.x; o1 += z*wv.y;
            }
            ((float2*)(outbase + ((size_t)r*512 + t)*64))[cg] = make_float2(o0, o1);
        }
        __syncthreads();
    }
    __pipeline_wait_prior(0);
}

__global__ void merge_kernel(const float* __restrict__ attn_w, float* __restrict__ out){
    int warp = (blockIdx.x*blockDim.x + threadIdx.x) >> 5;
    int lane = threadIdx.x & 31;
    if (warp >= 512*512) return;
    const size_t SS = 512ull*512*64;
    const float* p = g_outs + (size_t)warp*64;
    float aw0 = attn_w[lane], aw1 = attn_w[lane+32];
    float v0[3], v1[3], sc[3];
    #pragma unroll
    for (int si=0; si<3; si++){
        v0[si] = p[si*SS + lane];
        v1[si] = p[si*SS + lane + 32];
        float d = v0[si]*aw0 + v1[si]*aw1;
        #pragma unroll
        for (int o=16;o;o>>=1) d += __shfl_xor_sync(0xffffffffu, d, o);
        sc[si] = d;
    }
    float mx = fmaxf(sc[0], fmaxf(sc[1], sc[2]));
    float e0 = __expf(sc[0]-mx), e1 = __expf(sc[1]-mx), e2 = __expf(sc[2]-mx);
    float inv = __fdividef(1.0f, e0+e1+e2);
    float wt0 = e0*inv, wt1 = e1*inv, wt2 = e2*inv;
    out[(size_t)warp*64 + lane]      = v0[0]*wt0 + v0[1]*wt1 + v0[2]*wt2;
    out[(size_t)warp*64 + lane + 32] = v1[0]*wt0 + v1[1]*wt1 + v1[2]*wt2;
}

extern "C" void kernel_launch(void* const* d_in, const int* in_sizes, int n_in,
                              void* d_out, int out_size){
    const float* x     = (const float*)d_in[0];
    const float* gw0   = (const float*)d_in[1];
    const float* gb0   = (const float*)d_in[2];
    const float* gw1   = (const float*)d_in[3];
    const float* gb1   = (const float*)d_in[4];
    const float* mi_w  = (const float*)d_in[5];
    const float* mi_b  = (const float*)d_in[6];
    const float* mo_w  = (const float*)d_in[7];
    const float* mo_b  = (const float*)d_in[8];
    const float* w1    = (const float*)d_in[9];
    const float* b1    = (const float*)d_in[10];
    const float* w2    = (const float*)d_in[11];
    const float* b2    = (const float*)d_in[12];
    const float* lag   = (const float*)d_in[13];
    const float* lab   = (const float*)d_in[14];
    const float* logw  = (const float*)d_in[15];
    const float* lob   = (const float*)d_in[16];
    const float* rw0   = (const float*)d_in[17];
    const float* rb0   = (const float*)d_in[18];
    const float* rw1   = (const float*)d_in[19];
    const float* rb1   = (const float*)d_in[20];
    const float* attnw = (const float*)d_in[21];
    float* out = (float*)d_out;

    static int smem_set = 0;
    if (!smem_set){
        cudaFuncSetAttribute(xlstm_kernel, cudaFuncAttributeMaxDynamicSharedMemorySize, DYN_SMEM);
        smem_set = 1;
    }

    pack_gw_kernel<<<(3*128*256 + 255)/256, 256>>>(gw0, gw1);
    compute_wa_kernel<<<6, 256>>>(mi_w, mi_b, mo_w, mo_b);
    xlstm_kernel<<<NCTA, T, DYN_SMEM>>>(x, gb0, gb1, w1, b1, w2, b2,
                                        lag, lab, logw, lob, rw0, rb0, rw1, rb1);
    merge_kernel<<<(512*512*32 + 255)/256, 256>>>(attnw, out);
}